// round 4
// baseline (speedup 1.0000x reference)
#include <cuda_runtime.h>
#include <math.h>

#define S   512
#define B   64
#define H   256
#define NH  4
#define NHH 1024      // NH*H
#define NCTA 128

// ---------------- device globals (no runtime allocation allowed) ------------
__device__ float g_P[(size_t)S * H * B];       // [t][j][b]  : x@Wi.T + (layout jb)
__device__ float g_gate[(size_t)S * B * NH];   // [t][b][nh] : sigmoid gates
__device__ float g_cand[2][H * B];             // double-buffered cand, [j][b]
__device__ float g_sel[B * NHH];               // hcat at t = len-1
__device__ unsigned g_flags[NCTA * 8];         // grid-barrier flags, 32B apart

// ---------------- init: reset barrier flags each replay ---------------------
__global__ void init_kernel() {
    int i = blockIdx.x * blockDim.x + threadIdx.x;
    if (i < NCTA * 8) g_flags[i] = 0u;
}

// ---------------- gate precompute: g = sigmoid(d - 3*nh) --------------------
__global__ __launch_bounds__(256)
void gate_kernel(const float* __restrict__ fix_src) {
    int t = blockIdx.x;
    int tid = threadIdx.x;          // b = tid>>2, nh = tid&3
    int b = tid >> 2, nh = tid & 3;
    float d = fix_src[b * S + t];
    g_gate[(size_t)t * (B * NH) + tid] = 1.0f / (1.0f + expf(3.0f * (float)nh - d));
}

// ---------------- P precompute: P[t][j][b] = emb[src[b,t]] . Wi[j,:] --------
// 1024 blocks: t = bx>>1, b-half = bx&1 (32 b's). 256 threads = j.
__global__ __launch_bounds__(256, 2)
void p_kernel(const int* __restrict__ src, const float* __restrict__ emb,
              const float* __restrict__ Wi) {
    __shared__ float s_x[32][256];
    __shared__ int s_tok[32];
    const int t = blockIdx.x >> 1, bh = blockIdx.x & 1;
    const int tid = threadIdx.x;

    if (tid < 32) s_tok[tid] = src[(bh * 32 + tid) * S + t];
    __syncthreads();
    {   // stage 32 embedding rows (32 KB)
        int row = tid >> 3, seg = tid & 7;
        const float4* sp = (const float4*)(emb + (size_t)s_tok[row] * H) + seg * 8;
        float4* dp = (float4*)(&s_x[row][0]) + seg * 8;
        #pragma unroll
        for (int q = 0; q < 8; ++q) dp[q] = sp[q];
    }
    __syncthreads();

    float acc[32];
    #pragma unroll
    for (int m = 0; m < 32; ++m) acc[m] = 0.0f;
    const int j = tid;
    const float4* w4p = (const float4*)(Wi + (size_t)j * H);

    #pragma unroll 2
    for (int k4 = 0; k4 < 64; ++k4) {
        float4 wv = w4p[k4];
        #pragma unroll
        for (int m = 0; m < 32; ++m) {
            float4 xv = *(const float4*)&s_x[m][k4 * 4];
            acc[m] = fmaf(wv.x, xv.x, acc[m]);
            acc[m] = fmaf(wv.y, xv.y, acc[m]);
            acc[m] = fmaf(wv.z, xv.z, acc[m]);
            acc[m] = fmaf(wv.w, xv.w, acc[m]);
        }
    }
    float* out = g_P + (size_t)t * (H * B) + (size_t)j * B + bh * 32;
    #pragma unroll
    for (int m4 = 0; m4 < 8; ++m4)
        ((float4*)out)[m4] = make_float4(acc[m4 * 4], acc[m4 * 4 + 1],
                                         acc[m4 * 4 + 2], acc[m4 * 4 + 3]);
}

// ---------------- flag-based grid barrier (no atomics, monotonic) -----------
__device__ __forceinline__ void grid_barrier(unsigned& bcnt, int tid, int cid) {
    __syncthreads();                       // all prior STG issued by this CTA
    ++bcnt;
    if (tid == 0) {
        __threadfence();                   // order cand stores before flag
        *(volatile unsigned*)&g_flags[cid * 8] = bcnt;
    }
    if (tid < NCTA) {
        while (*(volatile unsigned*)&g_flags[tid * 8] < bcnt) __nanosleep(64);
    }
    __threadfence();                       // acquire: see others' cand stores
    __syncthreads();
}

// ---------------- persistent recurrent kernel -------------------------------
// 128 CTAs, CTA c owns output columns j = {2c, 2c+1}. 256 threads:
//   ks = tid>>7 (j'-split), jl = (tid>>6)&1, b = tid&63.
__global__ __launch_bounds__(256, 1)
void rnn_kernel(const int* __restrict__ input_len,
                const float* __restrict__ bi, const float* __restrict__ bhb,
                const float* __restrict__ Wh) {
    __shared__ float s_cand[128 * 64];   // staged cand chunk [j'c][b], 32 KB
    __shared__ float s_Wp[2048];         // packed Wh [j'][jl][nh], 8 KB
    __shared__ float s_y[512];           // ks-reduce buffer [jl*64+b][nh], 2 KB

    const int tid = threadIdx.x, cid = blockIdx.x;
    const int ks = tid >> 7, jl = (tid >> 6) & 1, b = tid & 63;
    const int j = cid * 2 + jl;

    // pack Wh rows for our two j's: s_Wp[(j'*2 + jl)*4 + nh] = Wh[j, nh*256+j']
    for (int u = tid; u < 2048; u += 256) {
        int jp = u >> 3, ujl = (u >> 2) & 1, nh = u & 3;
        s_Wp[u] = Wh[(size_t)(cid * 2 + ujl) * NHH + nh * H + jp];
    }

    const float bsum = bi[j] + bhb[j];
    const int mylen = input_len[b];
    float z0 = 0.f, z1 = 0.f, z2 = 0.f, z3 = 0.f;
    float h0 = 0.f, h1 = 0.f, h2 = 0.f, h3 = 0.f;
    unsigned bcnt = 0;

    // cand(0) = tanh(P[0] + bias)   (z = 0)
    if (ks == 0)
        g_cand[0][j * B + b] = tanhf(g_P[(size_t)j * B + b] + bsum);
    grid_barrier(bcnt, tid, cid);        // also covers s_Wp staging

    #pragma unroll 1
    for (int t = 0; t < S; ++t) {
        const int p = t & 1;
        float y0 = 0.f, y1 = 0.f, y2 = 0.f, y3 = 0.f;

        #pragma unroll 1
        for (int cc = 0; cc < 2; ++cc) {
            // stage 8192 floats of cand (chunk cc) into smem, coalesced
            const float4* gsrc = (const float4*)(g_cand[p] + cc * 8192);
            float4* sdst = (float4*)s_cand;
            #pragma unroll
            for (int q = 0; q < 8; ++q) sdst[tid + q * 256] = gsrc[tid + q * 256];
            __syncthreads();

            const float* wbase = s_Wp + (size_t)(cc * 128 + ks * 64) * 8 + jl * 4;
            const float* cbase = s_cand + (size_t)(ks * 64) * 64 + b;
            #pragma unroll 8
            for (int i = 0; i < 64; ++i) {
                float4 w4 = *(const float4*)(wbase + i * 8);  // warp-broadcast
                float cv = cbase[i * 64];                     // conflict-free
                y0 = fmaf(w4.x, cv, y0);
                y1 = fmaf(w4.y, cv, y1);
                y2 = fmaf(w4.z, cv, y2);
                y3 = fmaf(w4.w, cv, y3);
            }
            __syncthreads();    // chunk reads done before restage/overwrite
        }

        // reduce the two ks halves
        if (ks == 1)
            *(float4*)&s_y[(jl * 64 + b) * 4] = make_float4(y0, y1, y2, y3);
        __syncthreads();

        if (ks == 0) {
            float4 yo = *(const float4*)&s_y[(jl * 64 + b) * 4];
            y0 += yo.x; y1 += yo.y; y2 += yo.z; y3 += yo.w;

            float4 g4 = *(const float4*)&g_gate[(size_t)t * (B * NH) + b * 4];
            float cl = g_cand[p][j * B + b];     // cand(t) for our own (b,j)

            z0 = fmaf(g4.x, y0 - z0, z0);        // z' = z + g*(y - z)
            z1 = fmaf(g4.y, y1 - z1, z1);
            z2 = fmaf(g4.z, y2 - z2, z2);
            z3 = fmaf(g4.w, y3 - z3, z3);
            h0 = fmaf(g4.x, cl - h0, h0);        // h' = h + g*(cand - h)
            h1 = fmaf(g4.y, cl - h1, h1);
            h2 = fmaf(g4.z, cl - h2, h2);
            h3 = fmaf(g4.w, cl - h3, h3);

            if (t == mylen - 1) {
                g_sel[b * NHH + 0 * H + j] = h0;
                g_sel[b * NHH + 1 * H + j] = h1;
                g_sel[b * NHH + 2 * H + j] = h2;
                g_sel[b * NHH + 3 * H + j] = h3;
            }
            if (t < S - 1) {
                float pre = g_P[(size_t)(t + 1) * (H * B) + (size_t)j * B + b]
                            + bsum + z0 + z1 + z2 + z3;
                g_cand[p ^ 1][j * B + b] = tanhf(pre);
            }
        }
        grid_barrier(bcnt, tid, cid);
    }
}

// ---------------- readout ---------------------------------------------------
__global__ __launch_bounds__(256)
void final_fc_kernel(const float* __restrict__ fc1_W,
                     const float* __restrict__ fc1_b,
                     const float* __restrict__ fc2_W,
                     const float* __restrict__ fc2_b,
                     float* __restrict__ out) {
    __shared__ float selsh[NHH];
    __shared__ float red0[H];
    __shared__ float red1[H];
    const int b = blockIdx.x;
    const int j = threadIdx.x;

    #pragma unroll
    for (int i = 0; i < NH; ++i)
        selsh[i * H + j] = g_sel[b * NHH + i * H + j];
    __syncthreads();

    float s = fc1_b[j];
    const float4* w = (const float4*)(fc1_W + (size_t)j * NHH);
    #pragma unroll 4
    for (int k4 = 0; k4 < NHH / 4; ++k4) {
        float4 wv = w[k4];
        float4 sv = *(const float4*)&selsh[k4 * 4];
        s = fmaf(wv.x, sv.x, s);
        s = fmaf(wv.y, sv.y, s);
        s = fmaf(wv.z, sv.z, s);
        s = fmaf(wv.w, sv.w, s);
    }
    s = tanhf(s);
    red0[j] = s * fc2_W[j];
    red1[j] = s * fc2_W[H + j];
    __syncthreads();

    for (int stride = 128; stride >= 1; stride >>= 1) {
        if (j < stride) {
            red0[j] += red0[j + stride];
            red1[j] += red1[j + stride];
        }
        __syncthreads();
    }
    if (j == 0) {
        out[b * 2 + 0] = red0[0] + fc2_b[0];
        out[b * 2 + 1] = red1[0] + fc2_b[1];
    }
}

// ---------------------------------------------------------------------------
extern "C" void kernel_launch(void* const* d_in, const int* in_sizes, int n_in,
                              void* d_out, int out_size) {
    const int*   src       = (const int*)  d_in[0];
    const int*   input_len = (const int*)  d_in[1];
    const float* fix_src   = (const float*)d_in[2];
    const float* emb_table = (const float*)d_in[3];
    const float* Wi        = (const float*)d_in[4];
    const float* bi        = (const float*)d_in[5];
    const float* Wh        = (const float*)d_in[6];
    const float* bh        = (const float*)d_in[7];
    const float* fc1_W     = (const float*)d_in[8];
    const float* fc1_b     = (const float*)d_in[9];
    const float* fc2_W     = (const float*)d_in[10];
    const float* fc2_b     = (const float*)d_in[11];
    float* out = (float*)d_out;

    init_kernel<<<4, 256>>>();
    gate_kernel<<<S, 256>>>(fix_src);
    p_kernel<<<2 * S, 256>>>(src, emb_table, Wi);
    rnn_kernel<<<NCTA, 256>>>(input_len, bi, bh, Wh);
    final_fc_kernel<<<B, 256>>>(fc1_W, fc1_b, fc2_W, fc2_b, out);
}